// round 9
// baseline (speedup 1.0000x reference)
#include <cuda_runtime.h>
#include <cuda_bf16.h>
#include <cstdint>
#include <math_constants.h>

// Problem constants
#define NT 8192      // tokens = 8*32*32
#define KC 8192      // codebook size
#define DD 256       // embedding dim
#define BHW 1024     // 32*32
#define NELEM 2097152  // 8*256*32*32
#define CAP 64       // candidate list capacity per token
#define ILCAP 64     // inverted-index capacity per code
#define MARGIN 2.5e-4f  // bf16-input dot err (worst ~2e-5) + fp32 bucket (3e-5), 5x headroom

// Output layout (float32, concatenated in reference return order)
// NOTE: OFF_EMAW / OFF_EMB are == 1 (mod 4) -> NO vector stores there!
#define OFF_ZQ   0
#define OFF_LOSS 2097152
#define OFF_IDX  2097153
#define OFF_CS   2105345
#define OFF_EMAW 2113537
#define OFF_EMB  4210689

// ---------------- device scratch (no cudaMalloc allowed) ----------------
static __device__ __align__(16) __nv_bfloat16 g_zbf[(size_t)NT * DD];    // 4 MB
static __device__ __align__(16) __nv_bfloat16 g_ebf[(size_t)KC * DD];    // 4 MB
static __device__ __align__(16) float         g_zf[(size_t)NT * DD];     // 8 MB
static __device__ float         g_enorm[KC];
static __device__ unsigned      g_tokmax[NT];              // ordered-uint running max dot
static __device__ int           g_ccnt[NT];
static __device__ __align__(16) int2 g_cand[(size_t)NT * CAP];  // 4 MB
static __device__ __align__(16) int  g_idx[NT];
static __device__ int           g_icnt[KC];                // tokens per code (exact)
static __device__ int           g_ilist[(size_t)KC * ILCAP];    // 2 MB inverted index
static __device__ __align__(16) float g_dw[(size_t)KC * DD];    // 8 MB (overflow only)
static __device__ float         g_ncsraw[KC];
static __device__ float         g_red[2];                  // [0]=sum(new_cs), [1]=loss sum

// ordered-uint encoding of float: monotonic for unsigned compare
__device__ __forceinline__ unsigned ford(float f) {
    unsigned b = __float_as_uint(f);
    return (b & 0x80000000u) ? ~b : (b | 0x80000000u);
}
__device__ __forceinline__ float iford(unsigned u) {
    unsigned b = (u & 0x80000000u) ? (u & 0x7fffffffu) : ~u;
    return __uint_as_float(b);
}

// ---------------- K0a: per-code prep: bf16 convert, ||e||^2, zero scratch ----
__global__ __launch_bounds__(256) void k_prep(const float* __restrict__ emb) {
    __shared__ float sm[256];
    int k = blockIdx.x, tid = threadIdx.x;
    float v = emb[(size_t)k * DD + tid];
    g_ebf[(size_t)k * DD + tid] = __float2bfloat16(v);
    g_dw[(size_t)k * DD + tid] = 0.0f;
    sm[tid] = v * v;
    __syncthreads();
    #pragma unroll
    for (int o = 128; o > 0; o >>= 1) {
        if (tid < o) sm[tid] += sm[tid + o];
        __syncthreads();
    }
    if (tid == 0) {
        g_enorm[k] = sm[0];
        g_icnt[k] = 0;
        g_tokmax[k] = 0u;     // below ford of any finite value
        g_ccnt[k] = 0;
        if (k < 2) g_red[k] = 0.0f;
    }
}

// ---------------- K0c: transpose z [B,C,H,W] -> [t][d] (bf16 + fp32) --------
__global__ void k_transpose(const float* __restrict__ z) {
    __shared__ float tile[32][33];
    int b = blockIdx.z, d0 = blockIdx.y * 32, hw0 = blockIdx.x * 32;
    int x = threadIdx.x, y = threadIdx.y;
    const float* zb = z + (size_t)b * (DD * BHW);
    #pragma unroll
    for (int yy = y; yy < 32; yy += 8)
        tile[yy][x] = zb[(size_t)(d0 + yy) * BHW + hw0 + x];
    __syncthreads();
    #pragma unroll
    for (int yy = y; yy < 32; yy += 8) {
        float v = tile[x][yy];
        size_t o = (size_t)(b * BHW + hw0 + yy) * DD + d0 + x;
        g_zbf[o] = __float2bfloat16(v);
        g_zf[o] = v;
    }
}

// ---------------- K1: bf16 GEMM (z.e) with fused argmax/candidate epilogue --
// 512 threads, BM=128 tokens x BN=256 codes, warp grid 2x8 (64x32 per warp).
#define BM 128
#define BN 256
#define ASTRIDE 88   // 176B row stride: conflict-free for ldmatrix, 16B aligned
#define ABYTES (BM * ASTRIDE * 2)         // 22528
#define BBYTES (BN * ASTRIDE * 2)         // 45056
#define BUFBYTES (ABYTES + BBYTES)        // 67584 per stage
#define SMEM_GEMM (2 * BUFBYTES)          // double buffered = 135168

__device__ __forceinline__ void mma16816(float* c, const unsigned* a, const unsigned* b) {
    asm volatile(
        "mma.sync.aligned.m16n8k16.row.col.f32.bf16.bf16.f32 "
        "{%0,%1,%2,%3}, {%4,%5,%6,%7}, {%8,%9}, {%0,%1,%2,%3};\n"
        : "+f"(c[0]), "+f"(c[1]), "+f"(c[2]), "+f"(c[3])
        : "r"(a[0]), "r"(a[1]), "r"(a[2]), "r"(a[3]), "r"(b[0]), "r"(b[1]));
}

__device__ __forceinline__ void ldsm_x4(unsigned* r, uint32_t addr) {
    asm volatile("ldmatrix.sync.aligned.m8n8.x4.shared.b16 {%0,%1,%2,%3}, [%4];"
        : "=r"(r[0]), "=r"(r[1]), "=r"(r[2]), "=r"(r[3]) : "r"(addr));
}
__device__ __forceinline__ void ldsm_x2(unsigned* r, uint32_t addr) {
    asm volatile("ldmatrix.sync.aligned.m8n8.x2.shared.b16 {%0,%1}, [%2];"
        : "=r"(r[0]), "=r"(r[1]) : "r"(addr));
}

__device__ __forceinline__ void cpasync16(void* smem, const void* g) {
    unsigned s = (unsigned)__cvta_generic_to_shared(smem);
    asm volatile("cp.async.cg.shared.global [%0], [%1], 16;\n" :: "r"(s), "l"(g));
}
#define CP_COMMIT() asm volatile("cp.async.commit_group;\n" ::: "memory")
#define CP_WAIT(n)  asm volatile("cp.async.wait_group %0;\n" :: "n"(n) : "memory")

__device__ __forceinline__ void load_tile(char* buf, int it, int t0, int k0, int tid) {
    __nv_bfloat16* As = (__nv_bfloat16*)buf;
    __nv_bfloat16* Bs = (__nv_bfloat16*)(buf + ABYTES);
    #pragma unroll
    for (int p = 0; p < 2; ++p) {          // A: 128 rows x 64 cols
        int idx = p * 4096 + tid * 8;
        int row = idx >> 6, col = idx & 63;
        cpasync16(As + row * ASTRIDE + col,
                  g_zbf + (size_t)(t0 + row) * DD + it * 64 + col);
    }
    #pragma unroll
    for (int p = 0; p < 4; ++p) {          // B: 256 rows x 64 cols
        int idx = p * 4096 + tid * 8;
        int row = idx >> 6, col = idx & 63;
        cpasync16(Bs + row * ASTRIDE + col,
                  g_ebf + (size_t)(k0 + row) * DD + it * 64 + col);
    }
}

__global__ __launch_bounds__(512) void k_gemm() {
    extern __shared__ char dynbuf[];
    uint32_t sbase = (uint32_t)__cvta_generic_to_shared(dynbuf);
    int t0 = blockIdx.y * BM, k0 = blockIdx.x * BN;
    int tid = threadIdx.x;
    int w = tid >> 5, lane = tid & 31;
    int wm = w >> 3, wn = w & 7;           // 2 x 8 warp grid, 64x32 warp tile
    int g = lane >> 2, tg = lane & 3;
    int lr = lane & 7, quad = lane >> 3;

    // ldmatrix per-lane byte offsets (within a stage buffer)
    uint32_t a_off = ((wm * 64 + lr + (quad & 1) * 8) * ASTRIDE + (quad >> 1) * 8) * 2;
    uint32_t b_off = (uint32_t)ABYTES + ((wn * 32 + lr) * ASTRIDE) * 2
                   + ((quad & 1) ? 16u : 0u);

    float acc[4][4][4];
    #pragma unroll
    for (int mi = 0; mi < 4; ++mi)
        #pragma unroll
        for (int ni = 0; ni < 4; ++ni)
            #pragma unroll
            for (int r = 0; r < 4; ++r) acc[mi][ni][r] = 0.0f;

    load_tile(dynbuf, 0, t0, k0, tid);
    CP_COMMIT();

    for (int it = 0; it < 4; ++it) {
        if (it < 3) {
            load_tile(dynbuf + ((it + 1) & 1) * BUFBYTES, it + 1, t0, k0, tid);
            CP_COMMIT();
            CP_WAIT(1);
        } else {
            CP_WAIT(0);
        }
        __syncthreads();

        uint32_t bufb = sbase + (it & 1) * BUFBYTES;
        #pragma unroll
        for (int ks = 0; ks < 4; ++ks) {
            uint32_t kb2 = ks * 32;        // ks*16 elements * 2 bytes
            unsigned a[4][4], bfr[4][2];
            #pragma unroll
            for (int mi = 0; mi < 4; ++mi)
                ldsm_x4(a[mi], bufb + a_off + mi * (16 * ASTRIDE * 2) + kb2);
            #pragma unroll
            for (int ni = 0; ni < 4; ++ni)
                ldsm_x2(bfr[ni], bufb + b_off + ni * (8 * ASTRIDE * 2) + kb2);
            #pragma unroll
            for (int mi = 0; mi < 4; ++mi)
                #pragma unroll
                for (int ni = 0; ni < 4; ++ni)
                    mma16816(acc[mi][ni], a[mi], bfr[ni]);
        }
        __syncthreads();
    }

    // -------- fused epilogue: per-token running max + candidate append ------
    unsigned* srm = (unsigned*)dynbuf;          // [128] ordered-uint row max
    float*    sthr = (float*)(dynbuf + 512);    // [128] per-row threshold
    if (tid < 128) srm[tid] = 0u;
    __syncthreads();

    #pragma unroll
    for (int mi = 0; mi < 4; ++mi) {
        float m1 = -CUDART_INF_F, m2 = -CUDART_INF_F;
        #pragma unroll
        for (int ni = 0; ni < 4; ++ni) {
            m1 = fmaxf(m1, fmaxf(acc[mi][ni][0], acc[mi][ni][1]));
            m2 = fmaxf(m2, fmaxf(acc[mi][ni][2], acc[mi][ni][3]));
        }
        #pragma unroll
        for (int o = 1; o <= 2; o <<= 1) {
            m1 = fmaxf(m1, __shfl_xor_sync(0xffffffffu, m1, o));
            m2 = fmaxf(m2, __shfl_xor_sync(0xffffffffu, m2, o));
        }
        if (tg == 0) {
            int r1 = wm * 64 + mi * 16 + g;
            atomicMax(&srm[r1], ford(m1));
            atomicMax(&srm[r1 + 8], ford(m2));
        }
    }
    __syncthreads();

    if (tid < 128) {
        unsigned mine = srm[tid];
        unsigned old = atomicMax(&g_tokmax[t0 + tid], mine);
        unsigned cur = old > mine ? old : mine;
        sthr[tid] = iford(cur) - MARGIN;
    }
    __syncthreads();

    #pragma unroll
    for (int mi = 0; mi < 4; ++mi) {
        int r1 = wm * 64 + mi * 16 + g;
        float th1 = sthr[r1], th2 = sthr[r1 + 8];
        #pragma unroll
        for (int ni = 0; ni < 4; ++ni) {
            int c0 = k0 + wn * 32 + ni * 8 + tg * 2;
            #pragma unroll
            for (int h = 0; h < 2; ++h) {
                float v1 = acc[mi][ni][h];
                if (v1 >= th1) {
                    int t = t0 + r1;
                    int pos = atomicAdd(&g_ccnt[t], 1);
                    if (pos < CAP) g_cand[(size_t)t * CAP + pos] =
                        make_int2(c0 + h, __float_as_int(v1));
                }
                float v2 = acc[mi][ni][2 + h];
                if (v2 >= th2) {
                    int t = t0 + r1 + 8;
                    int pos = atomicAdd(&g_ccnt[t], 1);
                    if (pos < CAP) g_cand[(size_t)t * CAP + pos] =
                        make_int2(c0 + h, __float_as_int(v2));
                }
            }
        }
    }
}

// ---------------- K2: warp-per-token exact fp32 rescore (reference rounding)
// Reference scores d = (||z||^2 + ||e||^2) - 2*(z.e) in fp32; ||z||^2 ~ 256
// buckets scores to ulp(||z||^2). Argmin invariant to ulp-level shifts of our
// zn. Candidate lists are supersets of all possible reference winners (stale
// running-max thresholds only ADD candidates). Pre-prune against the list max
// drops those extras before any embedding-row load. Tie-break: lowest index.
// Winner goes into an inverted index (code -> tokens) instead of 256 dw
// atomics; >ILCAP tokens per code falls back to g_dw atomics (rare/never).
__global__ __launch_bounds__(256) void k_select(const float* __restrict__ emb,
                                                float* __restrict__ out) {
    int t = blockIdx.x * 8 + (threadIdx.x >> 5);
    int lane = threadIdx.x & 31;

    const float* zp = g_zf + (size_t)t * DD + lane * 8;
    float4 za = *(const float4*)zp;
    float4 zb = *(const float4*)(zp + 4);
    float zr[8] = {za.x, za.y, za.z, za.w, zb.x, zb.y, zb.z, zb.w};

    float zn = 0.0f;
    #pragma unroll
    for (int q = 0; q < 8; ++q) zn += zr[q] * zr[q];
    #pragma unroll
    for (int o = 16; o > 0; o >>= 1) zn += __shfl_xor_sync(0xffffffffu, zn, o);

    int cnt = g_ccnt[t];
    float bv = CUDART_INF_F; int bi = 0x7fffffff;

    if (cnt <= CAP) {
        // pre-prune: max of stored fp32 dots, keep only within MARGIN
        float pmax = -CUDART_INF_F;
        for (int c = lane; c < cnt; c += 32)
            pmax = fmaxf(pmax, __int_as_float(g_cand[(size_t)t * CAP + c].y));
        #pragma unroll
        for (int o = 16; o > 0; o >>= 1)
            pmax = fmaxf(pmax, __shfl_xor_sync(0xffffffffu, pmax, o));
        float pthr = pmax - MARGIN;

        for (int c = 0; c < cnt; ++c) {
            int2 cd = g_cand[(size_t)t * CAP + c];
            if (__int_as_float(cd.y) < pthr) continue;
            int j = cd.x;
            const float* e = emb + (size_t)j * DD + lane * 8;
            float4 ea = *(const float4*)e;
            float4 eb = *(const float4*)(e + 4);
            float p = zr[0] * ea.x + zr[1] * ea.y + zr[2] * ea.z + zr[3] * ea.w
                    + zr[4] * eb.x + zr[5] * eb.y + zr[6] * eb.z + zr[7] * eb.w;
            #pragma unroll
            for (int o = 16; o > 0; o >>= 1) p += __shfl_xor_sync(0xffffffffu, p, o);
            // all lanes hold identical p -> identical comparison, no divergence
            float s = __fsub_rn(__fadd_rn(zn, g_enorm[j]), __fmul_rn(2.0f, p));
            if (s < bv || (s == bv && j < bi)) { bv = s; bi = j; }
        }
    } else {
        // overflow fallback (practically unreachable): exact scan of all codes
        for (int j = lane; j < KC; j += 32) {
            const float* e = emb + (size_t)j * DD;
            float d0 = 0.f, d1 = 0.f, d2 = 0.f, d3 = 0.f;
            for (int d = 0; d < DD; d += 4) {
                d0 += g_zf[(size_t)t * DD + d]     * e[d];
                d1 += g_zf[(size_t)t * DD + d + 1] * e[d + 1];
                d2 += g_zf[(size_t)t * DD + d + 2] * e[d + 2];
                d3 += g_zf[(size_t)t * DD + d + 3] * e[d + 3];
            }
            float p = (d0 + d1) + (d2 + d3);
            float s = __fsub_rn(__fadd_rn(zn, g_enorm[j]), __fmul_rn(2.0f, p));
            if (s < bv || (s == bv && j < bi)) { bv = s; bi = j; }
        }
        #pragma unroll
        for (int o = 16; o > 0; o >>= 1) {
            float ov = __shfl_xor_sync(0xffffffffu, bv, o);
            int   oi = __shfl_xor_sync(0xffffffffu, bi, o);
            if (ov < bv || (ov == bv && oi < bi)) { bv = ov; bi = oi; }
        }
    }

    int pos = 0;
    if (lane == 0) {
        g_idx[t] = bi;
        out[OFF_IDX + t] = (float)bi;
        pos = atomicAdd(&g_icnt[bi], 1);
        if (pos < ILCAP) g_ilist[(size_t)bi * ILCAP + pos] = t;
    }
    pos = __shfl_sync(0xffffffffu, pos, 0);
    if (pos >= ILCAP) {     // overflow: rare fallback to scattered atomics
        float* dwp = g_dw + (size_t)bi * DD + lane * 8;
        #pragma unroll
        for (int q = 0; q < 8; ++q) atomicAdd(dwp + q, zr[q]);
    }
}

// ---------------- K3: new cluster size raw + global sum ----------------
__global__ void k_ncs(const float* __restrict__ cs) {
    __shared__ float sm[256];
    int k = blockIdx.x * 256 + threadIdx.x;
    float raw = cs[k] * 0.99f + 0.01f * (float)g_icnt[k];
    g_ncsraw[k] = raw;
    sm[threadIdx.x] = raw;
    __syncthreads();
    #pragma unroll
    for (int o = 128; o > 0; o >>= 1) {
        if (threadIdx.x < o) sm[threadIdx.x] += sm[threadIdx.x + o];
        __syncthreads();
    }
    if (threadIdx.x == 0) atomicAdd(&g_red[0], sm[0]);
}

// ---------------- K4: one block per code: gather dw from inverted index,
// ema_w, embedding, new_cs outputs (scalar stores: odd output offsets) -------
__global__ __launch_bounds__(256) void k_final(const float* __restrict__ emaw,
                                               float* __restrict__ out) {
    int k = blockIdx.x, d = threadIdx.x;
    int cl = g_icnt[k];
    if (cl > ILCAP) cl = ILCAP;
    float dw = g_dw[(size_t)k * DD + d];       // overflow residue (normally 0)
    for (int c = 0; c < cl; ++c) {
        int t = g_ilist[(size_t)k * ILCAP + c];
        dw += g_zf[(size_t)t * DD + d];
    }
    float n = g_red[0];
    float ncs = (g_ncsraw[k] + 1e-5f) / (n + 0.08192f) * n;
    float w = emaw[(size_t)k * DD + d] * 0.99f + 0.01f * dw;
    out[OFF_EMAW + k * DD + d] = w;
    out[OFF_EMB + k * DD + d] = w / ncs;
    if (d == 0) out[OFF_CS + k] = ncs;
}

// ---------------- K5: z_q gather (NCHW, float4) + loss partial sums ---------
__global__ __launch_bounds__(256) void k_zq(const float* __restrict__ z,
                                            const float* __restrict__ emb,
                                            float* __restrict__ out) {
    int i4 = blockIdx.x * 256 + threadIdx.x;   // over NELEM/4
    int i = i4 * 4;
    int b = i >> 18;
    int rem = i & 262143;
    int d = rem >> 10;
    int hw = rem & 1023;                       // hw % 4 == 0
    int n = (b << 10) | hw;
    int4 idx4 = *(const int4*)(g_idx + n);     // 4 consecutive tokens, same d
    float4 q4;
    q4.x = emb[(size_t)idx4.x * DD + d];
    q4.y = emb[(size_t)idx4.y * DD + d];
    q4.z = emb[(size_t)idx4.z * DD + d];
    q4.w = emb[(size_t)idx4.w * DD + d];
    float4 z4 = ((const float4*)z)[i4];
    ((float4*)(out + OFF_ZQ))[i4] = q4;        // OFF_ZQ = 0: 16B aligned
    float dx = q4.x - z4.x, dy = q4.y - z4.y, dz = q4.z - z4.z, dw = q4.w - z4.w;
    float s = dx * dx + dy * dy + dz * dz + dw * dw;
    #pragma unroll
    for (int o = 16; o > 0; o >>= 1) s += __shfl_down_sync(0xffffffffu, s, o);
    if ((threadIdx.x & 31) == 0) atomicAdd(&g_red[1], s);
}

// ---------------- K6: loss scalar ----------------
__global__ void k_tail(float* __restrict__ out) {
    out[OFF_LOSS] = 1.25f * g_red[1] / 2097152.0f;
}

// ---------------- launch ----------------
extern "C" void kernel_launch(void* const* d_in, const int* in_sizes, int n_in,
                              void* d_out, int out_size) {
    const float* z    = (const float*)d_in[0];
    const float* emb  = (const float*)d_in[1];
    const float* cs   = (const float*)d_in[2];
    const float* emaw = (const float*)d_in[3];
    float* out = (float*)d_out;

    cudaFuncSetAttribute(k_gemm, cudaFuncAttributeMaxDynamicSharedMemorySize, SMEM_GEMM);

    k_prep<<<KC, 256>>>(emb);
    k_transpose<<<dim3(32, 8, 8), dim3(32, 8)>>>(z);
    k_gemm<<<dim3(KC / BN, NT / BM), 512, SMEM_GEMM>>>();
    k_select<<<NT / 8, 256>>>(emb, out);
    k_ncs<<<KC / 256, 256>>>(cs);
    k_final<<<KC, 256>>>(emaw, out);
    k_zq<<<NELEM / 1024, 256>>>(z, emb, out);
    k_tail<<<1, 1>>>(out);
}

// round 10
// speedup vs baseline: 1.0848x; 1.0848x over previous
#include <cuda_runtime.h>
#include <cuda_bf16.h>
#include <cstdint>
#include <math_constants.h>

// Problem constants
#define NT 8192      // tokens = 8*32*32
#define KC 8192      // codebook size
#define DD 256       // embedding dim
#define BHW 1024     // 32*32
#define NELEM 2097152  // 8*256*32*32
#define CAP 64       // candidate list capacity per token
#define ILCAP 64     // inverted-index capacity per code
#define MARGIN 2.5e-4f  // bf16-input dot err (worst ~2e-5) + fp32 bucket (3e-5), 5x headroom

// Output layout (float32, concatenated in reference return order)
// NOTE: OFF_EMAW / OFF_EMB are == 1 (mod 4) -> NO vector stores there!
#define OFF_ZQ   0
#define OFF_LOSS 2097152
#define OFF_IDX  2097153
#define OFF_CS   2105345
#define OFF_EMAW 2113537
#define OFF_EMB  4210689

// ---------------- device scratch (no cudaMalloc allowed) ----------------
static __device__ __align__(16) __nv_bfloat16 g_zbf[(size_t)NT * DD];    // 4 MB
static __device__ __align__(16) __nv_bfloat16 g_ebf[(size_t)KC * DD];    // 4 MB
static __device__ __align__(16) float         g_zf[(size_t)NT * DD];     // 8 MB
static __device__ float         g_enorm[KC];
static __device__ unsigned      g_tokmax[NT];              // ordered-uint running max dot
static __device__ int           g_ccnt[NT];
static __device__ __align__(16) int2 g_cand[(size_t)NT * CAP];  // 4 MB
static __device__ __align__(16) int  g_idx[NT];
static __device__ int           g_icnt[KC];                // tokens per code (exact)
static __device__ int           g_ilist[(size_t)KC * ILCAP];    // 2 MB inverted index
static __device__ __align__(16) float g_dw[(size_t)KC * DD];    // 8 MB (overflow only)
static __device__ float         g_ncsraw[KC];
static __device__ float         g_red[2];                  // [0]=sum(new_cs), [1]=loss sum

// ordered-uint encoding of float: monotonic for unsigned compare
__device__ __forceinline__ unsigned ford(float f) {
    unsigned b = __float_as_uint(f);
    return (b & 0x80000000u) ? ~b : (b | 0x80000000u);
}
__device__ __forceinline__ float iford(unsigned u) {
    unsigned b = (u & 0x80000000u) ? (u & 0x7fffffffu) : ~u;
    return __uint_as_float(b);
}

// ---------------- K0a: per-code prep: bf16 convert, ||e||^2, zero scratch ----
__global__ __launch_bounds__(256) void k_prep(const float* __restrict__ emb) {
    __shared__ float sm[256];
    int k = blockIdx.x, tid = threadIdx.x;
    float v = emb[(size_t)k * DD + tid];
    g_ebf[(size_t)k * DD + tid] = __float2bfloat16(v);
    g_dw[(size_t)k * DD + tid] = 0.0f;
    sm[tid] = v * v;
    __syncthreads();
    #pragma unroll
    for (int o = 128; o > 0; o >>= 1) {
        if (tid < o) sm[tid] += sm[tid + o];
        __syncthreads();
    }
    if (tid == 0) {
        g_enorm[k] = sm[0];
        g_icnt[k] = 0;
        g_tokmax[k] = 0u;     // below ford of any finite value
        g_ccnt[k] = 0;
        if (k < 2) g_red[k] = 0.0f;
    }
}

// ---------------- K0c: transpose z [B,C,H,W] -> [t][d] (bf16 + fp32) --------
__global__ void k_transpose(const float* __restrict__ z) {
    __shared__ float tile[32][33];
    int b = blockIdx.z, d0 = blockIdx.y * 32, hw0 = blockIdx.x * 32;
    int x = threadIdx.x, y = threadIdx.y;
    const float* zb = z + (size_t)b * (DD * BHW);
    #pragma unroll
    for (int yy = y; yy < 32; yy += 8)
        tile[yy][x] = zb[(size_t)(d0 + yy) * BHW + hw0 + x];
    __syncthreads();
    #pragma unroll
    for (int yy = y; yy < 32; yy += 8) {
        float v = tile[x][yy];
        size_t o = (size_t)(b * BHW + hw0 + yy) * DD + d0 + x;
        g_zbf[o] = __float2bfloat16(v);
        g_zf[o] = v;
    }
}

// ---------------- K1: bf16 GEMM (z.e) with fused argmax/candidate epilogue --
// Round-8 proven shape: 256 threads, BM=BN=128, 2 CTAs/SM.
#define BM 128
#define BN 128
#define ASTRIDE 88   // 176B row stride: conflict-free for ldmatrix, 16B aligned
#define BUFBYTES (2 * BM * ASTRIDE * 2)   // As+Bs per stage = 45056 B
#define SMEM_GEMM (2 * BUFBYTES)          // double buffered = 90112 B

__device__ __forceinline__ void mma16816(float* c, const unsigned* a, const unsigned* b) {
    asm volatile(
        "mma.sync.aligned.m16n8k16.row.col.f32.bf16.bf16.f32 "
        "{%0,%1,%2,%3}, {%4,%5,%6,%7}, {%8,%9}, {%0,%1,%2,%3};\n"
        : "+f"(c[0]), "+f"(c[1]), "+f"(c[2]), "+f"(c[3])
        : "r"(a[0]), "r"(a[1]), "r"(a[2]), "r"(a[3]), "r"(b[0]), "r"(b[1]));
}

__device__ __forceinline__ void ldsm_x4(unsigned* r, uint32_t addr) {
    asm volatile("ldmatrix.sync.aligned.m8n8.x4.shared.b16 {%0,%1,%2,%3}, [%4];"
        : "=r"(r[0]), "=r"(r[1]), "=r"(r[2]), "=r"(r[3]) : "r"(addr));
}
__device__ __forceinline__ void ldsm_x2(unsigned* r, uint32_t addr) {
    asm volatile("ldmatrix.sync.aligned.m8n8.x2.shared.b16 {%0,%1}, [%2];"
        : "=r"(r[0]), "=r"(r[1]) : "r"(addr));
}

__device__ __forceinline__ void cpasync16(void* smem, const void* g) {
    unsigned s = (unsigned)__cvta_generic_to_shared(smem);
    asm volatile("cp.async.cg.shared.global [%0], [%1], 16;\n" :: "r"(s), "l"(g));
}
#define CP_COMMIT() asm volatile("cp.async.commit_group;\n" ::: "memory")
#define CP_WAIT(n)  asm volatile("cp.async.wait_group %0;\n" :: "n"(n) : "memory")

__device__ __forceinline__ void load_tile(char* buf, int it, int t0, int k0, int tid) {
    __nv_bfloat16* As = (__nv_bfloat16*)buf;
    __nv_bfloat16* Bs = (__nv_bfloat16*)(buf + BM * ASTRIDE * 2);
    #pragma unroll
    for (int p = 0; p < 4; ++p) {
        int idx = p * 2048 + tid * 8;
        int row = idx >> 6, col = idx & 63;
        cpasync16(As + row * ASTRIDE + col,
                  g_zbf + (size_t)(t0 + row) * DD + it * 64 + col);
        cpasync16(Bs + row * ASTRIDE + col,
                  g_ebf + (size_t)(k0 + row) * DD + it * 64 + col);
    }
}

__global__ __launch_bounds__(256) void k_gemm() {
    extern __shared__ char dynbuf[];
    uint32_t sbase = (uint32_t)__cvta_generic_to_shared(dynbuf);
    int t0 = blockIdx.y * BM, k0 = blockIdx.x * BN;
    int tid = threadIdx.x;
    int w = tid >> 5, lane = tid & 31;
    int wm = w >> 2, wn = w & 3;           // 2 x 4 warp grid, 64x32 warp tile
    int g = lane >> 2, tg = lane & 3;
    int lr = lane & 7, quad = lane >> 3;

    // ldmatrix per-lane byte offsets (within a stage buffer)
    uint32_t a_off = ((wm * 64 + lr + (quad & 1) * 8) * ASTRIDE + (quad >> 1) * 8) * 2;
    uint32_t b_off = (uint32_t)(BM * ASTRIDE * 2) + ((wn * 32 + lr) * ASTRIDE) * 2
                   + ((quad & 1) ? 16u : 0u);

    float acc[4][4][4];
    #pragma unroll
    for (int mi = 0; mi < 4; ++mi)
        #pragma unroll
        for (int ni = 0; ni < 4; ++ni)
            #pragma unroll
            for (int r = 0; r < 4; ++r) acc[mi][ni][r] = 0.0f;

    load_tile(dynbuf, 0, t0, k0, tid);
    CP_COMMIT();

    for (int it = 0; it < 4; ++it) {
        if (it < 3) {
            load_tile(dynbuf + ((it + 1) & 1) * BUFBYTES, it + 1, t0, k0, tid);
            CP_COMMIT();
            CP_WAIT(1);
        } else {
            CP_WAIT(0);
        }
        __syncthreads();

        uint32_t bufb = sbase + (it & 1) * BUFBYTES;
        #pragma unroll
        for (int ks = 0; ks < 4; ++ks) {
            uint32_t kb2 = ks * 32;        // ks*16 elements * 2 bytes
            unsigned a[4][4], bfr[4][2];
            #pragma unroll
            for (int mi = 0; mi < 4; ++mi)
                ldsm_x4(a[mi], bufb + a_off + mi * (16 * ASTRIDE * 2) + kb2);
            #pragma unroll
            for (int ni = 0; ni < 4; ++ni)
                ldsm_x2(bfr[ni], bufb + b_off + ni * (8 * ASTRIDE * 2) + kb2);
            #pragma unroll
            for (int mi = 0; mi < 4; ++mi)
                #pragma unroll
                for (int ni = 0; ni < 4; ++ni)
                    mma16816(acc[mi][ni], a[mi], bfr[ni]);
        }
        __syncthreads();
    }

    // -------- fused epilogue: per-token running max + candidate append ------
    unsigned* srm = (unsigned*)dynbuf;          // [128] ordered-uint row max
    float*    sthr = (float*)(dynbuf + 512);    // [128] per-row threshold
    if (tid < 128) srm[tid] = 0u;
    __syncthreads();

    #pragma unroll
    for (int mi = 0; mi < 4; ++mi) {
        float m1 = -CUDART_INF_F, m2 = -CUDART_INF_F;
        #pragma unroll
        for (int ni = 0; ni < 4; ++ni) {
            m1 = fmaxf(m1, fmaxf(acc[mi][ni][0], acc[mi][ni][1]));
            m2 = fmaxf(m2, fmaxf(acc[mi][ni][2], acc[mi][ni][3]));
        }
        #pragma unroll
        for (int o = 1; o <= 2; o <<= 1) {
            m1 = fmaxf(m1, __shfl_xor_sync(0xffffffffu, m1, o));
            m2 = fmaxf(m2, __shfl_xor_sync(0xffffffffu, m2, o));
        }
        if (tg == 0) {
            int r1 = wm * 64 + mi * 16 + g;
            atomicMax(&srm[r1], ford(m1));
            atomicMax(&srm[r1 + 8], ford(m2));
        }
    }
    __syncthreads();

    if (tid < 128) {
        unsigned mine = srm[tid];
        unsigned old = atomicMax(&g_tokmax[t0 + tid], mine);
        unsigned cur = old > mine ? old : mine;
        sthr[tid] = iford(cur) - MARGIN;
    }
    __syncthreads();

    #pragma unroll
    for (int mi = 0; mi < 4; ++mi) {
        int r1 = wm * 64 + mi * 16 + g;
        float th1 = sthr[r1], th2 = sthr[r1 + 8];
        #pragma unroll
        for (int ni = 0; ni < 4; ++ni) {
            int c0 = k0 + wn * 32 + ni * 8 + tg * 2;
            #pragma unroll
            for (int h = 0; h < 2; ++h) {
                float v1 = acc[mi][ni][h];
                if (v1 >= th1) {
                    int t = t0 + r1;
                    int pos = atomicAdd(&g_ccnt[t], 1);
                    if (pos < CAP) g_cand[(size_t)t * CAP + pos] =
                        make_int2(c0 + h, __float_as_int(v1));
                }
                float v2 = acc[mi][ni][2 + h];
                if (v2 >= th2) {
                    int t = t0 + r1 + 8;
                    int pos = atomicAdd(&g_ccnt[t], 1);
                    if (pos < CAP) g_cand[(size_t)t * CAP + pos] =
                        make_int2(c0 + h, __float_as_int(v2));
                }
            }
        }
    }
}

// ---------------- K2: warp-per-token exact fp32 rescore (reference rounding)
// Reference scores d = (||z||^2 + ||e||^2) - 2*(z.e) in fp32; ||z||^2 ~ 256
// buckets scores to ulp(||z||^2). Argmin invariant to ulp-level shifts of our
// zn. Candidate lists are supersets of all possible reference winners (stale
// running-max thresholds only ADD candidates). Pre-prune against the list max
// drops those extras before any embedding-row load. Tie-break: lowest index.
// Winner goes into an inverted index (code -> tokens) instead of 256 dw
// atomics; >ILCAP tokens per code falls back to g_dw atomics (rare/never).
__global__ __launch_bounds__(256) void k_select(const float* __restrict__ emb,
                                                float* __restrict__ out) {
    int t = blockIdx.x * 8 + (threadIdx.x >> 5);
    int lane = threadIdx.x & 31;

    const float* zp = g_zf + (size_t)t * DD + lane * 8;
    float4 za = *(const float4*)zp;
    float4 zb = *(const float4*)(zp + 4);
    float zr[8] = {za.x, za.y, za.z, za.w, zb.x, zb.y, zb.z, zb.w};

    float zn = 0.0f;
    #pragma unroll
    for (int q = 0; q < 8; ++q) zn += zr[q] * zr[q];
    #pragma unroll
    for (int o = 16; o > 0; o >>= 1) zn += __shfl_xor_sync(0xffffffffu, zn, o);

    int cnt = g_ccnt[t];
    float bv = CUDART_INF_F; int bi = 0x7fffffff;

    if (cnt <= CAP) {
        // pre-prune: max of stored fp32 dots, keep only within MARGIN
        float pmax = -CUDART_INF_F;
        for (int c = lane; c < cnt; c += 32)
            pmax = fmaxf(pmax, __int_as_float(g_cand[(size_t)t * CAP + c].y));
        #pragma unroll
        for (int o = 16; o > 0; o >>= 1)
            pmax = fmaxf(pmax, __shfl_xor_sync(0xffffffffu, pmax, o));
        float pthr = pmax - MARGIN;

        for (int c = 0; c < cnt; ++c) {
            int2 cd = g_cand[(size_t)t * CAP + c];
            if (__int_as_float(cd.y) < pthr) continue;
            int j = cd.x;
            const float* e = emb + (size_t)j * DD + lane * 8;
            float4 ea = *(const float4*)e;
            float4 eb = *(const float4*)(e + 4);
            float p = zr[0] * ea.x + zr[1] * ea.y + zr[2] * ea.z + zr[3] * ea.w
                    + zr[4] * eb.x + zr[5] * eb.y + zr[6] * eb.z + zr[7] * eb.w;
            #pragma unroll
            for (int o = 16; o > 0; o >>= 1) p += __shfl_xor_sync(0xffffffffu, p, o);
            // all lanes hold identical p -> identical comparison, no divergence
            float s = __fsub_rn(__fadd_rn(zn, g_enorm[j]), __fmul_rn(2.0f, p));
            if (s < bv || (s == bv && j < bi)) { bv = s; bi = j; }
        }
    } else {
        // overflow fallback (practically unreachable): exact scan of all codes
        for (int j = lane; j < KC; j += 32) {
            const float* e = emb + (size_t)j * DD;
            float d0 = 0.f, d1 = 0.f, d2 = 0.f, d3 = 0.f;
            for (int d = 0; d < DD; d += 4) {
                d0 += g_zf[(size_t)t * DD + d]     * e[d];
                d1 += g_zf[(size_t)t * DD + d + 1] * e[d + 1];
                d2 += g_zf[(size_t)t * DD + d + 2] * e[d + 2];
                d3 += g_zf[(size_t)t * DD + d + 3] * e[d + 3];
            }
            float p = (d0 + d1) + (d2 + d3);
            float s = __fsub_rn(__fadd_rn(zn, g_enorm[j]), __fmul_rn(2.0f, p));
            if (s < bv || (s == bv && j < bi)) { bv = s; bi = j; }
        }
        #pragma unroll
        for (int o = 16; o > 0; o >>= 1) {
            float ov = __shfl_xor_sync(0xffffffffu, bv, o);
            int   oi = __shfl_xor_sync(0xffffffffu, bi, o);
            if (ov < bv || (ov == bv && oi < bi)) { bv = ov; bi = oi; }
        }
    }

    int pos = 0;
    if (lane == 0) {
        g_idx[t] = bi;
        out[OFF_IDX + t] = (float)bi;
        pos = atomicAdd(&g_icnt[bi], 1);
        if (pos < ILCAP) g_ilist[(size_t)bi * ILCAP + pos] = t;
    }
    pos = __shfl_sync(0xffffffffu, pos, 0);
    if (pos >= ILCAP) {     // overflow: rare fallback to scattered atomics
        float* dwp = g_dw + (size_t)bi * DD + lane * 8;
        #pragma unroll
        for (int q = 0; q < 8; ++q) atomicAdd(dwp + q, zr[q]);
    }
}

// ---------------- K3: new cluster size raw + global sum ----------------
__global__ void k_ncs(const float* __restrict__ cs) {
    __shared__ float sm[256];
    int k = blockIdx.x * 256 + threadIdx.x;
    float raw = cs[k] * 0.99f + 0.01f * (float)g_icnt[k];
    g_ncsraw[k] = raw;
    sm[threadIdx.x] = raw;
    __syncthreads();
    #pragma unroll
    for (int o = 128; o > 0; o >>= 1) {
        if (threadIdx.x < o) sm[threadIdx.x] += sm[threadIdx.x + o];
        __syncthreads();
    }
    if (threadIdx.x == 0) atomicAdd(&g_red[0], sm[0]);
}

// ---------------- K4: one block per code: gather dw from inverted index,
// ema_w, embedding, new_cs outputs (scalar stores: odd output offsets) -------
__global__ __launch_bounds__(256) void k_final(const float* __restrict__ emaw,
                                               float* __restrict__ out) {
    int k = blockIdx.x, d = threadIdx.x;
    int cl = g_icnt[k];
    if (cl > ILCAP) cl = ILCAP;
    float dw = g_dw[(size_t)k * DD + d];       // overflow residue (normally 0)
    for (int c = 0; c < cl; ++c) {
        int t = g_ilist[(size_t)k * ILCAP + c];
        dw += g_zf[(size_t)t * DD + d];
    }
    float n = g_red[0];
    float ncs = (g_ncsraw[k] + 1e-5f) / (n + 0.08192f) * n;
    float w = emaw[(size_t)k * DD + d] * 0.99f + 0.01f * dw;
    out[OFF_EMAW + k * DD + d] = w;
    out[OFF_EMB + k * DD + d] = w / ncs;
    if (d == 0) out[OFF_CS + k] = ncs;
}

// ---------------- K5: z_q gather (NCHW, float4) + loss partial sums ---------
__global__ __launch_bounds__(256) void k_zq(const float* __restrict__ z,
                                            const float* __restrict__ emb,
                                            float* __restrict__ out) {
    int i4 = blockIdx.x * 256 + threadIdx.x;   // over NELEM/4
    int i = i4 * 4;
    int b = i >> 18;
    int rem = i & 262143;
    int d = rem >> 10;
    int hw = rem & 1023;                       // hw % 4 == 0
    int n = (b << 10) | hw;
    int4 idx4 = *(const int4*)(g_idx + n);     // 4 consecutive tokens, same d
    float4 q4;
    q4.x = emb[(size_t)idx4.x * DD + d];
    q4.y = emb[(size_t)idx4.y * DD + d];
    q4.z = emb[(size_t)idx4.z * DD + d];
    q4.w = emb[(size_t)idx4.w * DD + d];
    float4 z4 = ((const float4*)z)[i4];
    ((float4*)(out + OFF_ZQ))[i4] = q4;        // OFF_ZQ = 0: 16B aligned
    float dx = q4.x - z4.x, dy = q4.y - z4.y, dz = q4.z - z4.z, dw = q4.w - z4.w;
    float s = dx * dx + dy * dy + dz * dz + dw * dw;
    #pragma unroll
    for (int o = 16; o > 0; o >>= 1) s += __shfl_down_sync(0xffffffffu, s, o);
    if ((threadIdx.x & 31) == 0) atomicAdd(&g_red[1], s);
}

// ---------------- K6: loss scalar ----------------
__global__ void k_tail(float* __restrict__ out) {
    out[OFF_LOSS] = 1.25f * g_red[1] / 2097152.0f;
}

// ---------------- launch ----------------
extern "C" void kernel_launch(void* const* d_in, const int* in_sizes, int n_in,
                              void* d_out, int out_size) {
    const float* z    = (const float*)d_in[0];
    const float* emb  = (const float*)d_in[1];
    const float* cs   = (const float*)d_in[2];
    const float* emaw = (const float*)d_in[3];
    float* out = (float*)d_out;

    cudaFuncSetAttribute(k_gemm, cudaFuncAttributeMaxDynamicSharedMemorySize, SMEM_GEMM);

    k_prep<<<KC, 256>>>(emb);
    k_transpose<<<dim3(32, 8, 8), dim3(32, 8)>>>(z);
    k_gemm<<<dim3(KC / BN, NT / BM), 256, SMEM_GEMM>>>();
    k_select<<<NT / 8, 256>>>(emb, out);
    k_ncs<<<KC / 256, 256>>>(cs);
    k_final<<<KC, 256>>>(emaw, out);
    k_zq<<<NELEM / 1024, 256>>>(z, emb, out);
    k_tail<<<1, 1>>>(out);
}

// round 11
// speedup vs baseline: 1.0916x; 1.0062x over previous
#include <cuda_runtime.h>
#include <cuda_bf16.h>
#include <cstdint>
#include <math_constants.h>

// Problem constants
#define NT 8192      // tokens = 8*32*32
#define KC 8192      // codebook size
#define DD 256       // embedding dim
#define BHW 1024     // 32*32
#define NELEM 2097152  // 8*256*32*32
#define CAP 128      // candidate list capacity per token (64 overflowed: 64 cold-max tiles)
#define ILCAP 64     // inverted-index capacity per code
#define MARGIN 2.5e-4f  // bf16-input dot err (worst ~2e-5) + fp32 bucket (3e-5), 5x headroom

// Output layout (float32, concatenated in reference return order)
// NOTE: OFF_EMAW / OFF_EMB are == 1 (mod 4) -> NO vector stores there!
#define OFF_ZQ   0
#define OFF_LOSS 2097152
#define OFF_IDX  2097153
#define OFF_CS   2105345
#define OFF_EMAW 2113537
#define OFF_EMB  4210689

// ---------------- device scratch (no cudaMalloc allowed) ----------------
static __device__ __align__(16) __nv_bfloat16 g_zbf[(size_t)NT * DD];    // 4 MB
static __device__ __align__(16) __nv_bfloat16 g_ebf[(size_t)KC * DD];    // 4 MB
static __device__ __align__(16) float         g_zf[(size_t)NT * DD];     // 8 MB
static __device__ float         g_enorm[KC];
static __device__ unsigned      g_tokmax[NT];              // ordered-uint running max dot
static __device__ int           g_ccnt[NT];
static __device__ __align__(16) int2 g_cand[(size_t)NT * CAP];  // 8 MB
static __device__ __align__(16) int  g_idx[NT];
static __device__ int           g_icnt[KC];                // tokens per code (exact)
static __device__ int           g_ilist[(size_t)KC * ILCAP];    // 2 MB inverted index
static __device__ __align__(16) float g_dw[(size_t)KC * DD];    // 8 MB (overflow only)
static __device__ float         g_ncsraw[KC];
static __device__ int           g_ovf;                     // ILCAP overflow flag
static __device__ float         g_red[2];                  // [0]=sum(new_cs), [1]=loss sum

// ordered-uint encoding of float: monotonic for unsigned compare
__device__ __forceinline__ unsigned ford(float f) {
    unsigned b = __float_as_uint(f);
    return (b & 0x80000000u) ? ~b : (b | 0x80000000u);
}
__device__ __forceinline__ float iford(unsigned u) {
    unsigned b = (u & 0x80000000u) ? (u & 0x7fffffffu) : ~u;
    return __uint_as_float(b);
}

// ---------------- K0a: per-code prep: bf16 convert, ||e||^2, zero scratch ----
__global__ __launch_bounds__(256) void k_prep(const float* __restrict__ emb) {
    __shared__ float sm[256];
    int k = blockIdx.x, tid = threadIdx.x;
    float v = emb[(size_t)k * DD + tid];
    g_ebf[(size_t)k * DD + tid] = __float2bfloat16(v);
    sm[tid] = v * v;
    __syncthreads();
    #pragma unroll
    for (int o = 128; o > 0; o >>= 1) {
        if (tid < o) sm[tid] += sm[tid + o];
        __syncthreads();
    }
    if (tid == 0) {
        g_enorm[k] = sm[0];
        g_icnt[k] = 0;
        g_tokmax[k] = 0u;     // below ford of any finite value
        g_ccnt[k] = 0;
        if (k == 0) { g_red[0] = 0.0f; g_red[1] = 0.0f; g_ovf = 0; }
    }
}

// ---------------- K0b: zero the dw overflow buffer (launch #3 -> gemm is #4
// for the ncu capture window) ------------------------------------------------
__global__ __launch_bounds__(256) void k_zero() {
    int i = blockIdx.x * 256 + threadIdx.x;
    g_dw[i] = 0.0f;
}

// ---------------- K0c: transpose z [B,C,H,W] -> [t][d] (bf16 + fp32) --------
__global__ void k_transpose(const float* __restrict__ z) {
    __shared__ float tile[32][33];
    int b = blockIdx.z, d0 = blockIdx.y * 32, hw0 = blockIdx.x * 32;
    int x = threadIdx.x, y = threadIdx.y;
    const float* zb = z + (size_t)b * (DD * BHW);
    #pragma unroll
    for (int yy = y; yy < 32; yy += 8)
        tile[yy][x] = zb[(size_t)(d0 + yy) * BHW + hw0 + x];
    __syncthreads();
    #pragma unroll
    for (int yy = y; yy < 32; yy += 8) {
        float v = tile[x][yy];
        size_t o = (size_t)(b * BHW + hw0 + yy) * DD + d0 + x;
        g_zbf[o] = __float2bfloat16(v);
        g_zf[o] = v;
    }
}

// ---------------- K1: bf16 GEMM (z.e) with fused argmax/candidate epilogue --
// Proven shape: 256 threads, BM=BN=128, 2 CTAs/SM, ldmatrix + cp.async.
#define BM 128
#define BN 128
#define ASTRIDE 88   // 176B row stride: conflict-free for ldmatrix, 16B aligned
#define BUFBYTES (2 * BM * ASTRIDE * 2)   // As+Bs per stage = 45056 B
#define SMEM_GEMM (2 * BUFBYTES)          // double buffered = 90112 B

__device__ __forceinline__ void mma16816(float* c, const unsigned* a, const unsigned* b) {
    asm volatile(
        "mma.sync.aligned.m16n8k16.row.col.f32.bf16.bf16.f32 "
        "{%0,%1,%2,%3}, {%4,%5,%6,%7}, {%8,%9}, {%0,%1,%2,%3};\n"
        : "+f"(c[0]), "+f"(c[1]), "+f"(c[2]), "+f"(c[3])
        : "r"(a[0]), "r"(a[1]), "r"(a[2]), "r"(a[3]), "r"(b[0]), "r"(b[1]));
}

__device__ __forceinline__ void ldsm_x4(unsigned* r, uint32_t addr) {
    asm volatile("ldmatrix.sync.aligned.m8n8.x4.shared.b16 {%0,%1,%2,%3}, [%4];"
        : "=r"(r[0]), "=r"(r[1]), "=r"(r[2]), "=r"(r[3]) : "r"(addr));
}
__device__ __forceinline__ void ldsm_x2(unsigned* r, uint32_t addr) {
    asm volatile("ldmatrix.sync.aligned.m8n8.x2.shared.b16 {%0,%1}, [%2];"
        : "=r"(r[0]), "=r"(r[1]) : "r"(addr));
}

__device__ __forceinline__ void cpasync16(void* smem, const void* g) {
    unsigned s = (unsigned)__cvta_generic_to_shared(smem);
    asm volatile("cp.async.cg.shared.global [%0], [%1], 16;\n" :: "r"(s), "l"(g));
}
#define CP_COMMIT() asm volatile("cp.async.commit_group;\n" ::: "memory")
#define CP_WAIT(n)  asm volatile("cp.async.wait_group %0;\n" :: "n"(n) : "memory")

__device__ __forceinline__ void load_tile(char* buf, int it, int t0, int k0, int tid) {
    __nv_bfloat16* As = (__nv_bfloat16*)buf;
    __nv_bfloat16* Bs = (__nv_bfloat16*)(buf + BM * ASTRIDE * 2);
    #pragma unroll
    for (int p = 0; p < 4; ++p) {
        int idx = p * 2048 + tid * 8;
        int row = idx >> 6, col = idx & 63;
        cpasync16(As + row * ASTRIDE + col,
                  g_zbf + (size_t)(t0 + row) * DD + it * 64 + col);
        cpasync16(Bs + row * ASTRIDE + col,
                  g_ebf + (size_t)(k0 + row) * DD + it * 64 + col);
    }
}

__global__ __launch_bounds__(256) void k_gemm() {
    extern __shared__ char dynbuf[];
    uint32_t sbase = (uint32_t)__cvta_generic_to_shared(dynbuf);
    int t0 = blockIdx.y * BM, k0 = blockIdx.x * BN;
    int tid = threadIdx.x;
    int w = tid >> 5, lane = tid & 31;
    int wm = w >> 2, wn = w & 3;           // 2 x 4 warp grid, 64x32 warp tile
    int g = lane >> 2, tg = lane & 3;
    int lr = lane & 7, quad = lane >> 3;

    // ldmatrix per-lane byte offsets (within a stage buffer)
    uint32_t a_off = ((wm * 64 + lr + (quad & 1) * 8) * ASTRIDE + (quad >> 1) * 8) * 2;
    uint32_t b_off = (uint32_t)(BM * ASTRIDE * 2) + ((wn * 32 + lr) * ASTRIDE) * 2
                   + ((quad & 1) ? 16u : 0u);

    float acc[4][4][4];
    #pragma unroll
    for (int mi = 0; mi < 4; ++mi)
        #pragma unroll
        for (int ni = 0; ni < 4; ++ni)
            #pragma unroll
            for (int r = 0; r < 4; ++r) acc[mi][ni][r] = 0.0f;

    load_tile(dynbuf, 0, t0, k0, tid);
    CP_COMMIT();

    for (int it = 0; it < 4; ++it) {
        if (it < 3) {
            load_tile(dynbuf + ((it + 1) & 1) * BUFBYTES, it + 1, t0, k0, tid);
            CP_COMMIT();
            CP_WAIT(1);
        } else {
            CP_WAIT(0);
        }
        __syncthreads();

        uint32_t bufb = sbase + (it & 1) * BUFBYTES;
        #pragma unroll
        for (int ks = 0; ks < 4; ++ks) {
            uint32_t kb2 = ks * 32;        // ks*16 elements * 2 bytes
            unsigned a[4][4], bfr[4][2];
            #pragma unroll
            for (int mi = 0; mi < 4; ++mi)
                ldsm_x4(a[mi], bufb + a_off + mi * (16 * ASTRIDE * 2) + kb2);
            #pragma unroll
            for (int ni = 0; ni < 4; ++ni)
                ldsm_x2(bfr[ni], bufb + b_off + ni * (8 * ASTRIDE * 2) + kb2);
            #pragma unroll
            for (int mi = 0; mi < 4; ++mi)
                #pragma unroll
                for (int ni = 0; ni < 4; ++ni)
                    mma16816(acc[mi][ni], a[mi], bfr[ni]);
        }
        __syncthreads();
    }

    // -------- fused epilogue: per-token running max + candidate append ------
    unsigned* srm = (unsigned*)dynbuf;          // [128] ordered-uint row max
    float*    sthr = (float*)(dynbuf + 512);    // [128] per-row threshold
    if (tid < 128) srm[tid] = 0u;
    __syncthreads();

    #pragma unroll
    for (int mi = 0; mi < 4; ++mi) {
        float m1 = -CUDART_INF_F, m2 = -CUDART_INF_F;
        #pragma unroll
        for (int ni = 0; ni < 4; ++ni) {
            m1 = fmaxf(m1, fmaxf(acc[mi][ni][0], acc[mi][ni][1]));
            m2 = fmaxf(m2, fmaxf(acc[mi][ni][2], acc[mi][ni][3]));
        }
        #pragma unroll
        for (int o = 1; o <= 2; o <<= 1) {
            m1 = fmaxf(m1, __shfl_xor_sync(0xffffffffu, m1, o));
            m2 = fmaxf(m2, __shfl_xor_sync(0xffffffffu, m2, o));
        }
        if (tg == 0) {
            int r1 = wm * 64 + mi * 16 + g;
            atomicMax(&srm[r1], ford(m1));
            atomicMax(&srm[r1 + 8], ford(m2));
        }
    }
    __syncthreads();

    if (tid < 128) {
        unsigned mine = srm[tid];
        unsigned old = atomicMax(&g_tokmax[t0 + tid], mine);
        unsigned cur = old > mine ? old : mine;
        sthr[tid] = iford(cur) - MARGIN;
    }
    __syncthreads();

    #pragma unroll
    for (int mi = 0; mi < 4; ++mi) {
        int r1 = wm * 64 + mi * 16 + g;
        float th1 = sthr[r1], th2 = sthr[r1 + 8];
        #pragma unroll
        for (int ni = 0; ni < 4; ++ni) {
            int c0 = k0 + wn * 32 + ni * 8 + tg * 2;
            #pragma unroll
            for (int h = 0; h < 2; ++h) {
                float v1 = acc[mi][ni][h];
                if (v1 >= th1) {
                    int t = t0 + r1;
                    int pos = atomicAdd(&g_ccnt[t], 1);
                    if (pos < CAP) g_cand[(size_t)t * CAP + pos] =
                        make_int2(c0 + h, __float_as_int(v1));
                }
                float v2 = acc[mi][ni][2 + h];
                if (v2 >= th2) {
                    int t = t0 + r1 + 8;
                    int pos = atomicAdd(&g_ccnt[t], 1);
                    if (pos < CAP) g_cand[(size_t)t * CAP + pos] =
                        make_int2(c0 + h, __float_as_int(v2));
                }
            }
        }
    }
}

// ---------------- K2: warp-per-token exact fp32 rescore (reference rounding)
// Reference scores d = (||z||^2 + ||e||^2) - 2*(z.e) in fp32; ||z||^2 ~ 256
// buckets scores to ulp(||z||^2). Argmin invariant to ulp-level shifts of our
// zn. Candidate lists are supersets of all possible reference winners (stale
// running-max thresholds only ADD candidates). Pre-prune against the list max
// drops those extras before any embedding-row load. Tie-break: lowest index.
// Winner goes into an inverted index (code -> tokens) instead of 256 dw
// atomics; >ILCAP tokens per code falls back to g_dw atomics (rare/never).
__global__ __launch_bounds__(256) void k_select(const float* __restrict__ emb,
                                                float* __restrict__ out) {
    int t = blockIdx.x * 8 + (threadIdx.x >> 5);
    int lane = threadIdx.x & 31;

    const float* zp = g_zf + (size_t)t * DD + lane * 8;
    float4 za = *(const float4*)zp;
    float4 zb = *(const float4*)(zp + 4);
    float zr[8] = {za.x, za.y, za.z, za.w, zb.x, zb.y, zb.z, zb.w};

    float zn = 0.0f;
    #pragma unroll
    for (int q = 0; q < 8; ++q) zn += zr[q] * zr[q];
    #pragma unroll
    for (int o = 16; o > 0; o >>= 1) zn += __shfl_xor_sync(0xffffffffu, zn, o);

    int cnt = g_ccnt[t];
    float bv = CUDART_INF_F; int bi = 0x7fffffff;

    if (cnt <= CAP) {
        // pre-prune: max of stored fp32 dots, keep only within MARGIN
        float pmax = -CUDART_INF_F;
        for (int c = lane; c < cnt; c += 32)
            pmax = fmaxf(pmax, __int_as_float(g_cand[(size_t)t * CAP + c].y));
        #pragma unroll
        for (int o = 16; o > 0; o >>= 1)
            pmax = fmaxf(pmax, __shfl_xor_sync(0xffffffffu, pmax, o));
        float pthr = pmax - MARGIN;

        for (int c = 0; c < cnt; ++c) {
            int2 cd = g_cand[(size_t)t * CAP + c];
            if (__int_as_float(cd.y) < pthr) continue;
            int j = cd.x;
            const float* e = emb + (size_t)j * DD + lane * 8;
            float4 ea = *(const float4*)e;
            float4 eb = *(const float4*)(e + 4);
            float p = zr[0] * ea.x + zr[1] * ea.y + zr[2] * ea.z + zr[3] * ea.w
                    + zr[4] * eb.x + zr[5] * eb.y + zr[6] * eb.z + zr[7] * eb.w;
            #pragma unroll
            for (int o = 16; o > 0; o >>= 1) p += __shfl_xor_sync(0xffffffffu, p, o);
            // all lanes hold identical p -> identical comparison, no divergence
            float s = __fsub_rn(__fadd_rn(zn, g_enorm[j]), __fmul_rn(2.0f, p));
            if (s < bv || (s == bv && j < bi)) { bv = s; bi = j; }
        }
    } else {
        // overflow fallback: exact scan of all codes
        for (int j = lane; j < KC; j += 32) {
            const float* e = emb + (size_t)j * DD;
            float d0 = 0.f, d1 = 0.f, d2 = 0.f, d3 = 0.f;
            for (int d = 0; d < DD; d += 4) {
                d0 += g_zf[(size_t)t * DD + d]     * e[d];
                d1 += g_zf[(size_t)t * DD + d + 1] * e[d + 1];
                d2 += g_zf[(size_t)t * DD + d + 2] * e[d + 2];
                d3 += g_zf[(size_t)t * DD + d + 3] * e[d + 3];
            }
            float p = (d0 + d1) + (d2 + d3);
            float s = __fsub_rn(__fadd_rn(zn, g_enorm[j]), __fmul_rn(2.0f, p));
            if (s < bv || (s == bv && j < bi)) { bv = s; bi = j; }
        }
        #pragma unroll
        for (int o = 16; o > 0; o >>= 1) {
            float ov = __shfl_xor_sync(0xffffffffu, bv, o);
            int   oi = __shfl_xor_sync(0xffffffffu, bi, o);
            if (ov < bv || (ov == bv && oi < bi)) { bv = ov; bi = oi; }
        }
    }

    int pos = 0;
    if (lane == 0) {
        g_idx[t] = bi;
        out[OFF_IDX + t] = (float)bi;
        pos = atomicAdd(&g_icnt[bi], 1);
        if (pos < ILCAP) g_ilist[(size_t)bi * ILCAP + pos] = t;
        else g_ovf = 1;
    }
    pos = __shfl_sync(0xffffffffu, pos, 0);
    if (pos >= ILCAP) {     // overflow: rare fallback to scattered atomics
        float* dwp = g_dw + (size_t)bi * DD + lane * 8;
        #pragma unroll
        for (int q = 0; q < 8; ++q) atomicAdd(dwp + q, zr[q]);
    }
}

// ---------------- K3: new cluster size raw + global sum ----------------
__global__ void k_ncs(const float* __restrict__ cs) {
    __shared__ float sm[256];
    int k = blockIdx.x * 256 + threadIdx.x;
    float raw = cs[k] * 0.99f + 0.01f * (float)g_icnt[k];
    g_ncsraw[k] = raw;
    sm[threadIdx.x] = raw;
    __syncthreads();
    #pragma unroll
    for (int o = 128; o > 0; o >>= 1) {
        if (threadIdx.x < o) sm[threadIdx.x] += sm[threadIdx.x + o];
        __syncthreads();
    }
    if (threadIdx.x == 0) atomicAdd(&g_red[0], sm[0]);
}

// ---------------- K5: z_q gather (NCHW, float4) + loss partial sums ---------
__global__ __launch_bounds__(256) void k_zq(const float* __restrict__ z,
                                            const float* __restrict__ emb,
                                            float* __restrict__ out) {
    int i4 = blockIdx.x * 256 + threadIdx.x;   // over NELEM/4
    int i = i4 * 4;
    int b = i >> 18;
    int rem = i & 262143;
    int d = rem >> 10;
    int hw = rem & 1023;                       // hw % 4 == 0
    int n = (b << 10) | hw;
    int4 idx4 = *(const int4*)(g_idx + n);     // 4 consecutive tokens, same d
    float4 q4;
    q4.x = emb[(size_t)idx4.x * DD + d];
    q4.y = emb[(size_t)idx4.y * DD + d];
    q4.z = emb[(size_t)idx4.z * DD + d];
    q4.w = emb[(size_t)idx4.w * DD + d];
    float4 z4 = ((const float4*)z)[i4];
    ((float4*)(out + OFF_ZQ))[i4] = q4;        // OFF_ZQ = 0: 16B aligned
    float dx = q4.x - z4.x, dy = q4.y - z4.y, dz = q4.z - z4.z, dw = q4.w - z4.w;
    float s = dx * dx + dy * dy + dz * dz + dw * dw;
    #pragma unroll
    for (int o = 16; o > 0; o >>= 1) s += __shfl_down_sync(0xffffffffu, s, o);
    if ((threadIdx.x & 31) == 0) atomicAdd(&g_red[1], s);
}

// ---------------- K4: one block per code: gather dw from inverted index,
// ema_w, embedding, new_cs, loss outputs (scalar stores: odd output offsets) -
__global__ __launch_bounds__(256) void k_final(const float* __restrict__ emaw,
                                               float* __restrict__ out) {
    int k = blockIdx.x, d = threadIdx.x;
    int cl = g_icnt[k];
    float dw = 0.0f;
    if (cl > ILCAP) { cl = ILCAP; }
    if (g_ovf) dw = g_dw[(size_t)k * DD + d];  // overflow residue (normally skipped)
    for (int c = 0; c < cl; ++c) {
        int t = g_ilist[(size_t)k * ILCAP + c];
        dw += g_zf[(size_t)t * DD + d];
    }
    float n = g_red[0];
    float ncs = (g_ncsraw[k] + 1e-5f) / (n + 0.08192f) * n;
    float w = emaw[(size_t)k * DD + d] * 0.99f + 0.01f * dw;
    out[OFF_EMAW + k * DD + d] = w;
    out[OFF_EMB + k * DD + d] = w / ncs;
    if (d == 0) {
        out[OFF_CS + k] = ncs;
        if (k == 0) out[OFF_LOSS] = 1.25f * g_red[1] / 2097152.0f;
    }
}

// ---------------- launch ----------------
extern "C" void kernel_launch(void* const* d_in, const int* in_sizes, int n_in,
                              void* d_out, int out_size) {
    const float* z    = (const float*)d_in[0];
    const float* emb  = (const float*)d_in[1];
    const float* cs   = (const float*)d_in[2];
    const float* emaw = (const float*)d_in[3];
    float* out = (float*)d_out;

    cudaFuncSetAttribute(k_gemm, cudaFuncAttributeMaxDynamicSharedMemorySize, SMEM_GEMM);

    k_prep<<<KC, 256>>>(emb);
    k_transpose<<<dim3(32, 8, 8), dim3(32, 8)>>>(z);
    k_zero<<<KC * DD / 256, 256>>>();              // launch #3: gemm becomes #4 (ncu window)
    k_gemm<<<dim3(KC / BN, NT / BM), 256, SMEM_GEMM>>>();
    k_select<<<NT / 8, 256>>>(emb, out);
    k_ncs<<<KC / 256, 256>>>(cs);
    k_zq<<<NELEM / 1024, 256>>>(z, emb, out);
    k_final<<<KC, 256>>>(emaw, out);
}